// round 1
// baseline (speedup 1.0000x reference)
#include <cuda_runtime.h>
#include <math.h>

#define TILE 64
#define NT   256
#define HD   128
#define OD   32
#define IND  64
#define BMAX 16384
#define MAXLVL 6

// -------- device scratch (no allocations allowed) --------
__device__ float g_ha  [(size_t)MAXLVL * BMAX * HD];   // per-level h_a slots (root + second children)
__device__ float g_hai [(size_t)MAXLVL * BMAX * HD];   // per-level h_ai (ancestral GRU output)
__device__ float g_prob[(size_t)MAXLVL * BMAX * OD];   // per-level probs (for fraternal GRU)

__device__ __forceinline__ float sigm(float x) { return 1.0f / (1.0f + __expf(-x)); }

// ============================================================
// init: h0 = z @ z2h_w + z2h_b       [B,64] @ [64,128]
// ============================================================
__global__ __launch_bounds__(NT, 2)
void init_kernel(const float* __restrict__ z, const float* __restrict__ Wz,
                 const float* __restrict__ bz, float* __restrict__ h0)
{
    __shared__ __align__(16) float zs[TILE][IND + 4];
    const int row0 = blockIdx.x * TILE;
    const int tid  = threadIdx.x;

    for (int i = tid; i < TILE * (IND / 4); i += NT) {
        int r = i >> 4, c = i & 15;
        float4 v = reinterpret_cast<const float4*>(z + (size_t)(row0 + r) * IND)[c];
        *reinterpret_cast<float4*>(&zs[r][c * 4]) = v;
    }
    __syncthreads();

    const int w = tid >> 5, l = tid & 31;
    #pragma unroll 1
    for (int p = 0; p < 2; ++p) {
        const int rb = w * 8 + p * 4;
        float bv[4];
        { float4 t = *reinterpret_cast<const float4*>(bz + 4 * l); bv[0]=t.x; bv[1]=t.y; bv[2]=t.z; bv[3]=t.w; }
        float acc[4][4];
        #pragma unroll
        for (int i = 0; i < 4; ++i)
            #pragma unroll
            for (int j = 0; j < 4; ++j) acc[i][j] = bv[j];

        #pragma unroll 2
        for (int k = 0; k < IND; ++k) {
            float wv[4];
            { float4 t = *reinterpret_cast<const float4*>(Wz + k * HD + 4 * l); wv[0]=t.x; wv[1]=t.y; wv[2]=t.z; wv[3]=t.w; }
            #pragma unroll
            for (int i = 0; i < 4; ++i) {
                float zv = zs[rb + i][k];
                #pragma unroll
                for (int j = 0; j < 4; ++j) acc[i][j] = fmaf(zv, wv[j], acc[i][j]);
            }
        }
        #pragma unroll
        for (int i = 0; i < 4; ++i)
            *reinterpret_cast<float4*>(h0 + (size_t)(row0 + rb + i) * HD + 4 * l)
                = make_float4(acc[i][0], acc[i][1], acc[i][2], acc[i][3]);
    }
}

// ============================================================
// node: pred = h@Wo+bo (emit), probs = softmax(pred),
//       h_ai = GRU_a(probs, h)
// ============================================================
__global__ __launch_bounds__(NT, 2)
void node_kernel(const float* __restrict__ hin,
                 const float* __restrict__ Wo, const float* __restrict__ bo,
                 const float* __restrict__ Wi, const float* __restrict__ bi,
                 const float* __restrict__ Wh, const float* __restrict__ bh,
                 float* __restrict__ pred_out, float* __restrict__ probs_out,
                 float* __restrict__ hout)
{
    __shared__ __align__(16) float hs[TILE][HD + 4];
    __shared__ __align__(16) float ps[TILE][OD + 4];
    const int row0 = blockIdx.x * TILE;
    const int tid  = threadIdx.x;

    for (int i = tid; i < TILE * (HD / 4); i += NT) {
        int r = i >> 5, c = i & 31;
        float4 v = reinterpret_cast<const float4*>(hin + (size_t)(row0 + r) * HD)[c];
        *reinterpret_cast<float4*>(&hs[r][c * 4]) = v;
    }
    __syncthreads();

    // ---- pred + softmax ----
    {
        const int r = tid >> 2, q = tid & 3;      // 64 rows x 4 lanes/row; o = q*8 + j
        float acc[8];
        #pragma unroll
        for (int j = 0; j < 8; ++j) acc[j] = bo[q * 8 + j];
        #pragma unroll 4
        for (int k = 0; k < HD; ++k) {
            float hv = hs[r][k];
            float w0[4], w1[4];
            { float4 t = *reinterpret_cast<const float4*>(Wo + k * OD + q * 8);     w0[0]=t.x; w0[1]=t.y; w0[2]=t.z; w0[3]=t.w; }
            { float4 t = *reinterpret_cast<const float4*>(Wo + k * OD + q * 8 + 4); w1[0]=t.x; w1[1]=t.y; w1[2]=t.z; w1[3]=t.w; }
            #pragma unroll
            for (int j = 0; j < 4; ++j) { acc[j] = fmaf(hv, w0[j], acc[j]); acc[4 + j] = fmaf(hv, w1[j], acc[4 + j]); }
        }
        float* po = pred_out + (size_t)(row0 + r) * OD;
        *reinterpret_cast<float4*>(po + q * 8)     = make_float4(acc[0], acc[1], acc[2], acc[3]);
        *reinterpret_cast<float4*>(po + q * 8 + 4) = make_float4(acc[4], acc[5], acc[6], acc[7]);

        float m = acc[0];
        #pragma unroll
        for (int j = 1; j < 8; ++j) m = fmaxf(m, acc[j]);
        m = fmaxf(m, __shfl_xor_sync(0xffffffffu, m, 1));
        m = fmaxf(m, __shfl_xor_sync(0xffffffffu, m, 2));
        float s = 0.0f;
        #pragma unroll
        for (int j = 0; j < 8; ++j) { acc[j] = __expf(acc[j] - m); s += acc[j]; }
        s += __shfl_xor_sync(0xffffffffu, s, 1);
        s += __shfl_xor_sync(0xffffffffu, s, 2);
        float inv = 1.0f / s;
        float* qo = probs_out + (size_t)(row0 + r) * OD;
        #pragma unroll
        for (int j = 0; j < 8; ++j) {
            float pv = acc[j] * inv;
            ps[r][q * 8 + j] = pv;
            qo[q * 8 + j] = pv;
        }
    }
    __syncthreads();

    // ---- GRU_a gates ----
    const int w = tid >> 5, l = tid & 31;
    const float* Wi0 = Wi;                const float* Wi1 = Wi + OD * HD;  const float* Wi2 = Wi + 2 * OD * HD;
    const float* Wh0 = Wh;                const float* Wh1 = Wh + HD * HD;  const float* Wh2 = Wh + 2 * HD * HD;

    #pragma unroll 1
    for (int p = 0; p < 2; ++p) {
        const int rb = w * 8 + p * 4;
        float a0[4][4], a1[4][4], a2i[4][4], a2h[4][4];
        #pragma unroll
        for (int i = 0; i < 4; ++i)
            #pragma unroll
            for (int j = 0; j < 4; ++j) { a0[i][j] = 0.f; a1[i][j] = 0.f; a2i[i][j] = 0.f; a2h[i][j] = 0.f; }

        #pragma unroll 2
        for (int k = 0; k < OD; ++k) {
            float w0[4], w1[4], w2[4];
            { float4 t = *reinterpret_cast<const float4*>(Wi0 + k * HD + 4 * l); w0[0]=t.x; w0[1]=t.y; w0[2]=t.z; w0[3]=t.w; }
            { float4 t = *reinterpret_cast<const float4*>(Wi1 + k * HD + 4 * l); w1[0]=t.x; w1[1]=t.y; w1[2]=t.z; w1[3]=t.w; }
            { float4 t = *reinterpret_cast<const float4*>(Wi2 + k * HD + 4 * l); w2[0]=t.x; w2[1]=t.y; w2[2]=t.z; w2[3]=t.w; }
            #pragma unroll
            for (int i = 0; i < 4; ++i) {
                float pv = ps[rb + i][k];
                #pragma unroll
                for (int j = 0; j < 4; ++j) {
                    a0[i][j]  = fmaf(pv, w0[j], a0[i][j]);
                    a1[i][j]  = fmaf(pv, w1[j], a1[i][j]);
                    a2i[i][j] = fmaf(pv, w2[j], a2i[i][j]);
                }
            }
        }
        #pragma unroll 2
        for (int k = 0; k < HD; ++k) {
            float w0[4], w1[4], w2[4];
            { float4 t = *reinterpret_cast<const float4*>(Wh0 + k * HD + 4 * l); w0[0]=t.x; w0[1]=t.y; w0[2]=t.z; w0[3]=t.w; }
            { float4 t = *reinterpret_cast<const float4*>(Wh1 + k * HD + 4 * l); w1[0]=t.x; w1[1]=t.y; w1[2]=t.z; w1[3]=t.w; }
            { float4 t = *reinterpret_cast<const float4*>(Wh2 + k * HD + 4 * l); w2[0]=t.x; w2[1]=t.y; w2[2]=t.z; w2[3]=t.w; }
            #pragma unroll
            for (int i = 0; i < 4; ++i) {
                float hv = hs[rb + i][k];
                #pragma unroll
                for (int j = 0; j < 4; ++j) {
                    a0[i][j]  = fmaf(hv, w0[j], a0[i][j]);
                    a1[i][j]  = fmaf(hv, w1[j], a1[i][j]);
                    a2h[i][j] = fmaf(hv, w2[j], a2h[i][j]);
                }
            }
        }
        float bi0[4], bi1[4], bi2[4], bh0[4], bh1[4], bh2[4];
        { float4 t = *reinterpret_cast<const float4*>(bi + 0 * HD + 4 * l); bi0[0]=t.x; bi0[1]=t.y; bi0[2]=t.z; bi0[3]=t.w; }
        { float4 t = *reinterpret_cast<const float4*>(bi + 1 * HD + 4 * l); bi1[0]=t.x; bi1[1]=t.y; bi1[2]=t.z; bi1[3]=t.w; }
        { float4 t = *reinterpret_cast<const float4*>(bi + 2 * HD + 4 * l); bi2[0]=t.x; bi2[1]=t.y; bi2[2]=t.z; bi2[3]=t.w; }
        { float4 t = *reinterpret_cast<const float4*>(bh + 0 * HD + 4 * l); bh0[0]=t.x; bh0[1]=t.y; bh0[2]=t.z; bh0[3]=t.w; }
        { float4 t = *reinterpret_cast<const float4*>(bh + 1 * HD + 4 * l); bh1[0]=t.x; bh1[1]=t.y; bh1[2]=t.z; bh1[3]=t.w; }
        { float4 t = *reinterpret_cast<const float4*>(bh + 2 * HD + 4 * l); bh2[0]=t.x; bh2[1]=t.y; bh2[2]=t.z; bh2[3]=t.w; }

        #pragma unroll
        for (int i = 0; i < 4; ++i) {
            float out[4];
            #pragma unroll
            for (int j = 0; j < 4; ++j) {
                float rg = sigm(a0[i][j] + bi0[j] + bh0[j]);
                float zg = sigm(a1[i][j] + bi1[j] + bh1[j]);
                float ng = tanhf(a2i[i][j] + bi2[j] + rg * (a2h[i][j] + bh2[j]));
                float hv = hs[rb + i][4 * l + j];
                out[j] = (1.0f - zg) * ng + zg * hv;
            }
            *reinterpret_cast<float4*>(hout + (size_t)(row0 + rb + i) * HD + 4 * l)
                = make_float4(out[0], out[1], out[2], out[3]);
        }
    }
}

// ============================================================
// frat: h_f = GRU_f(probs_f, h_ai);
//       h2  = tanh(h_f @ u_f_w + u_f_b + h_a @ u_a_w + u_a_b)
// ============================================================
__global__ __launch_bounds__(NT, 2)
void frat_kernel(const float* __restrict__ probsf,
                 const float* __restrict__ haif,
                 const float* __restrict__ hA,
                 const float* __restrict__ Wi, const float* __restrict__ bi,
                 const float* __restrict__ Wh, const float* __restrict__ bh,
                 const float* __restrict__ ufw, const float* __restrict__ ufb,
                 const float* __restrict__ uaw, const float* __restrict__ uab,
                 float* __restrict__ hout)
{
    __shared__ __align__(16) float hs[TILE][HD + 4];   // h_ai, overwritten in-place with h_f
    __shared__ __align__(16) float ps[TILE][OD + 4];
    const int row0 = blockIdx.x * TILE;
    const int tid  = threadIdx.x;

    for (int i = tid; i < TILE * (HD / 4); i += NT) {
        int r = i >> 5, c = i & 31;
        float4 v = reinterpret_cast<const float4*>(haif + (size_t)(row0 + r) * HD)[c];
        *reinterpret_cast<float4*>(&hs[r][c * 4]) = v;
    }
    for (int i = tid; i < TILE * (OD / 4); i += NT) {
        int r = i >> 3, c = i & 7;
        float4 v = reinterpret_cast<const float4*>(probsf + (size_t)(row0 + r) * OD)[c];
        *reinterpret_cast<float4*>(&ps[r][c * 4]) = v;
    }
    __syncthreads();

    const int w = tid >> 5, l = tid & 31;
    const float* Wi0 = Wi;  const float* Wi1 = Wi + OD * HD;  const float* Wi2 = Wi + 2 * OD * HD;
    const float* Wh0 = Wh;  const float* Wh1 = Wh + HD * HD;  const float* Wh2 = Wh + 2 * HD * HD;

    // ---- phase 1: GRU_f, write h_f in place over hs (rows are warp-exclusive) ----
    #pragma unroll 1
    for (int p = 0; p < 2; ++p) {
        const int rb = w * 8 + p * 4;
        float a0[4][4], a1[4][4], a2i[4][4], a2h[4][4];
        #pragma unroll
        for (int i = 0; i < 4; ++i)
            #pragma unroll
            for (int j = 0; j < 4; ++j) { a0[i][j] = 0.f; a1[i][j] = 0.f; a2i[i][j] = 0.f; a2h[i][j] = 0.f; }

        #pragma unroll 2
        for (int k = 0; k < OD; ++k) {
            float w0[4], w1[4], w2[4];
            { float4 t = *reinterpret_cast<const float4*>(Wi0 + k * HD + 4 * l); w0[0]=t.x; w0[1]=t.y; w0[2]=t.z; w0[3]=t.w; }
            { float4 t = *reinterpret_cast<const float4*>(Wi1 + k * HD + 4 * l); w1[0]=t.x; w1[1]=t.y; w1[2]=t.z; w1[3]=t.w; }
            { float4 t = *reinterpret_cast<const float4*>(Wi2 + k * HD + 4 * l); w2[0]=t.x; w2[1]=t.y; w2[2]=t.z; w2[3]=t.w; }
            #pragma unroll
            for (int i = 0; i < 4; ++i) {
                float pv = ps[rb + i][k];
                #pragma unroll
                for (int j = 0; j < 4; ++j) {
                    a0[i][j]  = fmaf(pv, w0[j], a0[i][j]);
                    a1[i][j]  = fmaf(pv, w1[j], a1[i][j]);
                    a2i[i][j] = fmaf(pv, w2[j], a2i[i][j]);
                }
            }
        }
        #pragma unroll 2
        for (int k = 0; k < HD; ++k) {
            float w0[4], w1[4], w2[4];
            { float4 t = *reinterpret_cast<const float4*>(Wh0 + k * HD + 4 * l); w0[0]=t.x; w0[1]=t.y; w0[2]=t.z; w0[3]=t.w; }
            { float4 t = *reinterpret_cast<const float4*>(Wh1 + k * HD + 4 * l); w1[0]=t.x; w1[1]=t.y; w1[2]=t.z; w1[3]=t.w; }
            { float4 t = *reinterpret_cast<const float4*>(Wh2 + k * HD + 4 * l); w2[0]=t.x; w2[1]=t.y; w2[2]=t.z; w2[3]=t.w; }
            #pragma unroll
            for (int i = 0; i < 4; ++i) {
                float hv = hs[rb + i][k];
                #pragma unroll
                for (int j = 0; j < 4; ++j) {
                    a0[i][j]  = fmaf(hv, w0[j], a0[i][j]);
                    a1[i][j]  = fmaf(hv, w1[j], a1[i][j]);
                    a2h[i][j] = fmaf(hv, w2[j], a2h[i][j]);
                }
            }
        }
        float bi0[4], bi1[4], bi2[4], bh0[4], bh1[4], bh2[4];
        { float4 t = *reinterpret_cast<const float4*>(bi + 0 * HD + 4 * l); bi0[0]=t.x; bi0[1]=t.y; bi0[2]=t.z; bi0[3]=t.w; }
        { float4 t = *reinterpret_cast<const float4*>(bi + 1 * HD + 4 * l); bi1[0]=t.x; bi1[1]=t.y; bi1[2]=t.z; bi1[3]=t.w; }
        { float4 t = *reinterpret_cast<const float4*>(bi + 2 * HD + 4 * l); bi2[0]=t.x; bi2[1]=t.y; bi2[2]=t.z; bi2[3]=t.w; }
        { float4 t = *reinterpret_cast<const float4*>(bh + 0 * HD + 4 * l); bh0[0]=t.x; bh0[1]=t.y; bh0[2]=t.z; bh0[3]=t.w; }
        { float4 t = *reinterpret_cast<const float4*>(bh + 1 * HD + 4 * l); bh1[0]=t.x; bh1[1]=t.y; bh1[2]=t.z; bh1[3]=t.w; }
        { float4 t = *reinterpret_cast<const float4*>(bh + 2 * HD + 4 * l); bh2[0]=t.x; bh2[1]=t.y; bh2[2]=t.z; bh2[3]=t.w; }

        float hf[4][4];
        #pragma unroll
        for (int i = 0; i < 4; ++i)
            #pragma unroll
            for (int j = 0; j < 4; ++j) {
                float rg = sigm(a0[i][j] + bi0[j] + bh0[j]);
                float zg = sigm(a1[i][j] + bi1[j] + bh1[j]);
                float ng = tanhf(a2i[i][j] + bi2[j] + rg * (a2h[i][j] + bh2[j]));
                float hv = hs[rb + i][4 * l + j];
                hf[i][j] = (1.0f - zg) * ng + zg * hv;
            }
        __syncwarp();   // all lanes done reading rows rb..rb+3 before overwrite
        #pragma unroll
        for (int i = 0; i < 4; ++i)
            #pragma unroll
            for (int j = 0; j < 4; ++j) hs[rb + i][4 * l + j] = hf[i][j];
        __syncwarp();
    }
    __syncthreads();

    // ---- phase 2: h2 = tanh(h_f @ ufw + ufb + h_a @ uaw + uab) ----
    #pragma unroll 1
    for (int p = 0; p < 2; ++p) {
        const int rb = w * 8 + p * 4;
        float bfv[4], bav[4];
        { float4 t = *reinterpret_cast<const float4*>(ufb + 4 * l); bfv[0]=t.x; bfv[1]=t.y; bfv[2]=t.z; bfv[3]=t.w; }
        { float4 t = *reinterpret_cast<const float4*>(uab + 4 * l); bav[0]=t.x; bav[1]=t.y; bav[2]=t.z; bav[3]=t.w; }
        float acc[4][4];
        #pragma unroll
        for (int i = 0; i < 4; ++i)
            #pragma unroll
            for (int j = 0; j < 4; ++j) acc[i][j] = bfv[j] + bav[j];

        #pragma unroll 2
        for (int k = 0; k < HD; ++k) {
            float wf[4], wa[4];
            { float4 t = *reinterpret_cast<const float4*>(ufw + k * HD + 4 * l); wf[0]=t.x; wf[1]=t.y; wf[2]=t.z; wf[3]=t.w; }
            { float4 t = *reinterpret_cast<const float4*>(uaw + k * HD + 4 * l); wa[0]=t.x; wa[1]=t.y; wa[2]=t.z; wa[3]=t.w; }
            #pragma unroll
            for (int i = 0; i < 4; ++i) {
                float hfv = hs[rb + i][k];
                float hav = __ldg(hA + (size_t)(row0 + rb + i) * HD + k);
                #pragma unroll
                for (int j = 0; j < 4; ++j) {
                    acc[i][j] = fmaf(hfv, wf[j], acc[i][j]);
                    acc[i][j] = fmaf(hav, wa[j], acc[i][j]);
                }
            }
        }
        #pragma unroll
        for (int i = 0; i < 4; ++i)
            *reinterpret_cast<float4*>(hout + (size_t)(row0 + rb + i) * HD + 4 * l)
                = make_float4(tanhf(acc[i][0]), tanhf(acc[i][1]), tanhf(acc[i][2]), tanhf(acc[i][3]));
    }
}

// ============================================================
// host: preorder scheduler
// ============================================================
struct SchedCtx {
    const float* in[18];
    float* out;
    float *ha, *hai, *prob;
    int B, grid, idx;
};

static void sched_node(SchedCtx& S, int lvl, const float* hA, int d)
{
    node_kernel<<<S.grid, NT>>>(hA,
        S.in[3], S.in[4],                       // h2o_w, h2o_b
        S.in[5], S.in[6], S.in[7], S.in[8],     // gru_a wi, bi, wh, bh
        S.out + (size_t)S.idx * S.B * OD,
        S.prob + (size_t)lvl * S.B * OD,
        S.hai  + (size_t)lvl * S.B * HD);
    S.idx++;
    if (d > 0) {
        const float* h_ai = S.hai + (size_t)lvl * S.B * HD;
        sched_node(S, lvl + 1, h_ai, d - 1);                       // first child
        frat_kernel<<<S.grid, NT>>>(
            S.prob + (size_t)(lvl + 1) * S.B * OD,                  // first child's probs
            h_ai, hA,
            S.in[9], S.in[10], S.in[11], S.in[12],                  // gru_f wi, bi, wh, bh
            S.in[15], S.in[16],                                     // u_f_w, u_f_b
            S.in[13], S.in[14],                                     // u_a_w, u_a_b
            S.ha + (size_t)(lvl + 1) * S.B * HD);
        sched_node(S, lvl + 1, S.ha + (size_t)(lvl + 1) * S.B * HD, d - 1);  // second child
    }
}

extern "C" void kernel_launch(void* const* d_in, const int* in_sizes, int n_in,
                              void* d_out, int out_size)
{
    SchedCtx S;
    for (int i = 0; i < n_in && i < 18; ++i) S.in[i] = (const float*)d_in[i];
    S.out = (float*)d_out;
    S.B = in_sizes[0] / IND;
    if (S.B <= 0 || S.B > BMAX) return;
    S.grid = S.B / TILE;
    S.idx = 0;

    int n_nodes = out_size / (S.B * OD);
    int depth = 0; { int nn = 1; while (nn < n_nodes && depth < MAXLVL - 1) { nn = 2 * nn + 1; depth++; } }

    cudaGetSymbolAddress((void**)&S.ha,   g_ha);
    cudaGetSymbolAddress((void**)&S.hai,  g_hai);
    cudaGetSymbolAddress((void**)&S.prob, g_prob);

    // h0 = z @ z2h_w + z2h_b  -> g_ha level 0
    init_kernel<<<S.grid, NT>>>(S.in[0], S.in[1], S.in[2], S.ha);

    sched_node(S, 0, S.ha, depth);
}

// round 2
// speedup vs baseline: 1.4341x; 1.4341x over previous
#include <cuda_runtime.h>
#include <math.h>

#define TILE 32
#define NT   256
#define HD   128
#define OD   32
#define IND  64
#define BMAX 16384
#define MAXLVL 6

typedef unsigned long long ull;

// -------- device scratch (no allocations allowed) --------
__device__ float g_ha  [(size_t)MAXLVL * BMAX * HD];
__device__ float g_hai [(size_t)MAXLVL * BMAX * HD];
__device__ float g_prob[(size_t)MAXLVL * BMAX * OD];

__device__ __forceinline__ float sigm(float x) { return 1.0f / (1.0f + __expf(-x)); }

// ---- packed fp32x2 helpers (sm_103a) ----
__device__ __forceinline__ ull pack2(float lo, float hi) {
    ull r; asm("mov.b64 %0, {%1, %2};" : "=l"(r) : "f"(lo), "f"(hi)); return r;
}
__device__ __forceinline__ void unpack2(ull v, float& lo, float& hi) {
    asm("mov.b64 {%0, %1}, %2;" : "=f"(lo), "=f"(hi) : "l"(v));
}
__device__ __forceinline__ ull dup2(float x) {
    ull r; asm("mov.b64 %0, {%1, %1};" : "=l"(r) : "f"(x)); return r;
}
__device__ __forceinline__ ull fma2(ull a, ull b, ull c) {
    ull d; asm("fma.rn.f32x2 %0, %1, %2, %3;" : "=l"(d) : "l"(a), "l"(b), "l"(c)); return d;
}

// ============================================================
// init: h0 = z @ z2h_w + z2h_b     [B,64] @ [64,128]
// ============================================================
__global__ __launch_bounds__(NT, 2)
void init_kernel(const float* __restrict__ z, const float* __restrict__ Wz,
                 const float* __restrict__ bz, float* __restrict__ h0)
{
    __shared__ __align__(16) float zs[TILE][IND + 4];
    const int row0 = blockIdx.x * TILE;
    const int tid  = threadIdx.x;

    for (int i = tid; i < TILE * (IND / 4); i += NT) {
        int r = i >> 4, c = i & 15;
        float4 v = reinterpret_cast<const float4*>(z + (size_t)(row0 + r) * IND)[c];
        *reinterpret_cast<float4*>(&zs[r][c * 4]) = v;
    }
    __syncthreads();

    const int w = tid >> 5, l = tid & 31;
    const int rb = w * 4;
    ull acc[4][2];
    {
        float4 t = *reinterpret_cast<const float4*>(bz + 4 * l);
        ull b0 = pack2(t.x, t.y), b1 = pack2(t.z, t.w);
        #pragma unroll
        for (int i = 0; i < 4; ++i) { acc[i][0] = b0; acc[i][1] = b1; }
    }
    #pragma unroll 4
    for (int k = 0; k < IND; ++k) {
        float4 t = *reinterpret_cast<const float4*>(Wz + k * HD + 4 * l);
        ull w0 = pack2(t.x, t.y), w1 = pack2(t.z, t.w);
        #pragma unroll
        for (int i = 0; i < 4; ++i) {
            ull zv = dup2(zs[rb + i][k]);
            acc[i][0] = fma2(zv, w0, acc[i][0]);
            acc[i][1] = fma2(zv, w1, acc[i][1]);
        }
    }
    #pragma unroll
    for (int i = 0; i < 4; ++i) {
        float x0, x1, x2, x3;
        unpack2(acc[i][0], x0, x1); unpack2(acc[i][1], x2, x3);
        *reinterpret_cast<float4*>(h0 + (size_t)(row0 + rb + i) * HD + 4 * l)
            = make_float4(x0, x1, x2, x3);
    }
}

// ============================================================
// node: pred = h@Wo+bo (emit), probs = softmax(pred),
//       h_ai = GRU_a(probs, h)
// ============================================================
__global__ __launch_bounds__(NT, 2)
void node_kernel(const float* __restrict__ hin,
                 const float* __restrict__ Wo, const float* __restrict__ bo,
                 const float* __restrict__ Wi, const float* __restrict__ bi,
                 const float* __restrict__ Wh, const float* __restrict__ bh,
                 float* __restrict__ pred_out, float* __restrict__ probs_out,
                 float* __restrict__ hout)
{
    __shared__ __align__(16) float hs[TILE][HD + 4];
    __shared__ __align__(16) float ps[TILE][OD + 4];
    const int row0 = blockIdx.x * TILE;
    const int tid  = threadIdx.x;

    for (int i = tid; i < TILE * (HD / 4); i += NT) {
        int r = i >> 5, c = i & 31;
        float4 v = reinterpret_cast<const float4*>(hin + (size_t)(row0 + r) * HD)[c];
        *reinterpret_cast<float4*>(&hs[r][c * 4]) = v;
    }
    __syncthreads();

    // ---- pred + softmax (warp-local rows: warp w owns rows 4w..4w+3) ----
    {
        const int r = tid >> 3, q = tid & 7;   // 8 lanes per row, 4 cols each
        ull a0 = 0, a1 = 0;
        {
            float4 t = *reinterpret_cast<const float4*>(bo + q * 4);
            a0 = pack2(t.x, t.y); a1 = pack2(t.z, t.w);
        }
        #pragma unroll 4
        for (int k = 0; k < HD; ++k) {
            float4 t = *reinterpret_cast<const float4*>(Wo + k * OD + q * 4);
            ull hv = dup2(hs[r][k]);
            a0 = fma2(hv, pack2(t.x, t.y), a0);
            a1 = fma2(hv, pack2(t.z, t.w), a1);
        }
        float acc[4];
        unpack2(a0, acc[0], acc[1]); unpack2(a1, acc[2], acc[3]);
        *reinterpret_cast<float4*>(pred_out + (size_t)(row0 + r) * OD + q * 4)
            = make_float4(acc[0], acc[1], acc[2], acc[3]);

        float m = fmaxf(fmaxf(acc[0], acc[1]), fmaxf(acc[2], acc[3]));
        m = fmaxf(m, __shfl_xor_sync(0xffffffffu, m, 1));
        m = fmaxf(m, __shfl_xor_sync(0xffffffffu, m, 2));
        m = fmaxf(m, __shfl_xor_sync(0xffffffffu, m, 4));
        float s = 0.0f;
        #pragma unroll
        for (int j = 0; j < 4; ++j) { acc[j] = __expf(acc[j] - m); s += acc[j]; }
        s += __shfl_xor_sync(0xffffffffu, s, 1);
        s += __shfl_xor_sync(0xffffffffu, s, 2);
        s += __shfl_xor_sync(0xffffffffu, s, 4);
        float inv = 1.0f / s;
        float pv[4];
        #pragma unroll
        for (int j = 0; j < 4; ++j) { pv[j] = acc[j] * inv; ps[r][q * 4 + j] = pv[j]; }
        *reinterpret_cast<float4*>(probs_out + (size_t)(row0 + r) * OD + q * 4)
            = make_float4(pv[0], pv[1], pv[2], pv[3]);
    }
    __syncwarp();   // ps rows are warp-local; GRU below reads only this warp's rows

    // ---- GRU_a gates: warp w rows 4w..4w+3, lane l cols 4l..4l+3 ----
    const int w = tid >> 5, l = tid & 31;
    const int rb = w * 4;
    const float* Wi0 = Wi;  const float* Wi1 = Wi + OD * HD;  const float* Wi2 = Wi + 2 * OD * HD;
    const float* Wh0 = Wh;  const float* Wh1 = Wh + HD * HD;  const float* Wh2 = Wh + 2 * HD * HD;

    ull a0[4][2], a1[4][2], a2i[4][2], a2h[4][2];
    #pragma unroll
    for (int i = 0; i < 4; ++i) {
        a0[i][0] = a0[i][1] = 0; a1[i][0] = a1[i][1] = 0;
        a2i[i][0] = a2i[i][1] = 0; a2h[i][0] = a2h[i][1] = 0;
    }

    #pragma unroll 4
    for (int k = 0; k < OD; ++k) {
        float4 t0 = *reinterpret_cast<const float4*>(Wi0 + k * HD + 4 * l);
        float4 t1 = *reinterpret_cast<const float4*>(Wi1 + k * HD + 4 * l);
        float4 t2 = *reinterpret_cast<const float4*>(Wi2 + k * HD + 4 * l);
        ull w00 = pack2(t0.x, t0.y), w01 = pack2(t0.z, t0.w);
        ull w10 = pack2(t1.x, t1.y), w11 = pack2(t1.z, t1.w);
        ull w20 = pack2(t2.x, t2.y), w21 = pack2(t2.z, t2.w);
        #pragma unroll
        for (int i = 0; i < 4; ++i) {
            ull pv = dup2(ps[rb + i][k]);
            a0[i][0]  = fma2(pv, w00, a0[i][0]);  a0[i][1]  = fma2(pv, w01, a0[i][1]);
            a1[i][0]  = fma2(pv, w10, a1[i][0]);  a1[i][1]  = fma2(pv, w11, a1[i][1]);
            a2i[i][0] = fma2(pv, w20, a2i[i][0]); a2i[i][1] = fma2(pv, w21, a2i[i][1]);
        }
    }
    #pragma unroll 4
    for (int k = 0; k < HD; ++k) {
        float4 t0 = *reinterpret_cast<const float4*>(Wh0 + k * HD + 4 * l);
        float4 t1 = *reinterpret_cast<const float4*>(Wh1 + k * HD + 4 * l);
        float4 t2 = *reinterpret_cast<const float4*>(Wh2 + k * HD + 4 * l);
        ull w00 = pack2(t0.x, t0.y), w01 = pack2(t0.z, t0.w);
        ull w10 = pack2(t1.x, t1.y), w11 = pack2(t1.z, t1.w);
        ull w20 = pack2(t2.x, t2.y), w21 = pack2(t2.z, t2.w);
        #pragma unroll
        for (int i = 0; i < 4; ++i) {
            ull hv = dup2(hs[rb + i][k]);
            a0[i][0]  = fma2(hv, w00, a0[i][0]);  a0[i][1]  = fma2(hv, w01, a0[i][1]);
            a1[i][0]  = fma2(hv, w10, a1[i][0]);  a1[i][1]  = fma2(hv, w11, a1[i][1]);
            a2h[i][0] = fma2(hv, w20, a2h[i][0]); a2h[i][1] = fma2(hv, w21, a2h[i][1]);
        }
    }

    float bi0[4], bi1[4], bi2[4], bh0[4], bh1[4], bh2[4];
    { float4 t = *reinterpret_cast<const float4*>(bi + 0 * HD + 4 * l); bi0[0]=t.x; bi0[1]=t.y; bi0[2]=t.z; bi0[3]=t.w; }
    { float4 t = *reinterpret_cast<const float4*>(bi + 1 * HD + 4 * l); bi1[0]=t.x; bi1[1]=t.y; bi1[2]=t.z; bi1[3]=t.w; }
    { float4 t = *reinterpret_cast<const float4*>(bi + 2 * HD + 4 * l); bi2[0]=t.x; bi2[1]=t.y; bi2[2]=t.z; bi2[3]=t.w; }
    { float4 t = *reinterpret_cast<const float4*>(bh + 0 * HD + 4 * l); bh0[0]=t.x; bh0[1]=t.y; bh0[2]=t.z; bh0[3]=t.w; }
    { float4 t = *reinterpret_cast<const float4*>(bh + 1 * HD + 4 * l); bh1[0]=t.x; bh1[1]=t.y; bh1[2]=t.z; bh1[3]=t.w; }
    { float4 t = *reinterpret_cast<const float4*>(bh + 2 * HD + 4 * l); bh2[0]=t.x; bh2[1]=t.y; bh2[2]=t.z; bh2[3]=t.w; }

    #pragma unroll
    for (int i = 0; i < 4; ++i) {
        float out[4];
        #pragma unroll
        for (int pr = 0; pr < 2; ++pr) {
            float g0a, g0b, g1a, g1b, nia, nib, nha, nhb;
            unpack2(a0[i][pr], g0a, g0b);  unpack2(a1[i][pr], g1a, g1b);
            unpack2(a2i[i][pr], nia, nib); unpack2(a2h[i][pr], nha, nhb);
            int j0 = pr * 2;
            {
                float rg = sigm(g0a + bi0[j0] + bh0[j0]);
                float zg = sigm(g1a + bi1[j0] + bh1[j0]);
                float ng = tanhf(nia + bi2[j0] + rg * (nha + bh2[j0]));
                float hv = hs[rb + i][4 * l + j0];
                out[j0] = (1.0f - zg) * ng + zg * hv;
            }
            {
                float rg = sigm(g0b + bi0[j0 + 1] + bh0[j0 + 1]);
                float zg = sigm(g1b + bi1[j0 + 1] + bh1[j0 + 1]);
                float ng = tanhf(nib + bi2[j0 + 1] + rg * (nhb + bh2[j0 + 1]));
                float hv = hs[rb + i][4 * l + j0 + 1];
                out[j0 + 1] = (1.0f - zg) * ng + zg * hv;
            }
        }
        *reinterpret_cast<float4*>(hout + (size_t)(row0 + rb + i) * HD + 4 * l)
            = make_float4(out[0], out[1], out[2], out[3]);
    }
}

// ============================================================
// frat: h_f = GRU_f(probs_f, h_ai);
//       h2  = tanh(h_f @ u_f_w + u_f_b + h_a @ u_a_w + u_a_b)
// ============================================================
__global__ __launch_bounds__(NT, 2)
void frat_kernel(const float* __restrict__ probsf,
                 const float* __restrict__ haif,
                 const float* __restrict__ hA,
                 const float* __restrict__ Wi, const float* __restrict__ bi,
                 const float* __restrict__ Wh, const float* __restrict__ bh,
                 const float* __restrict__ ufw, const float* __restrict__ ufb,
                 const float* __restrict__ uaw, const float* __restrict__ uab,
                 float* __restrict__ hout)
{
    __shared__ __align__(16) float hs [TILE][HD + 4];  // h_ai, overwritten with h_f
    __shared__ __align__(16) float has[TILE][HD + 4];  // h_a (ancestral)
    __shared__ __align__(16) float ps [TILE][OD + 4];
    const int row0 = blockIdx.x * TILE;
    const int tid  = threadIdx.x;

    for (int i = tid; i < TILE * (HD / 4); i += NT) {
        int r = i >> 5, c = i & 31;
        float4 v = reinterpret_cast<const float4*>(haif + (size_t)(row0 + r) * HD)[c];
        *reinterpret_cast<float4*>(&hs[r][c * 4]) = v;
        float4 u = reinterpret_cast<const float4*>(hA + (size_t)(row0 + r) * HD)[c];
        *reinterpret_cast<float4*>(&has[r][c * 4]) = u;
    }
    for (int i = tid; i < TILE * (OD / 4); i += NT) {
        int r = i >> 3, c = i & 7;
        float4 v = reinterpret_cast<const float4*>(probsf + (size_t)(row0 + r) * OD)[c];
        *reinterpret_cast<float4*>(&ps[r][c * 4]) = v;
    }
    __syncthreads();

    const int w = tid >> 5, l = tid & 31;
    const int rb = w * 4;
    const float* Wi0 = Wi;  const float* Wi1 = Wi + OD * HD;  const float* Wi2 = Wi + 2 * OD * HD;
    const float* Wh0 = Wh;  const float* Wh1 = Wh + HD * HD;  const float* Wh2 = Wh + 2 * HD * HD;

    // ---- phase 1: GRU_f, h_f written in place over hs (rows warp-private) ----
    {
        ull a0[4][2], a1[4][2], a2i[4][2], a2h[4][2];
        #pragma unroll
        for (int i = 0; i < 4; ++i) {
            a0[i][0] = a0[i][1] = 0; a1[i][0] = a1[i][1] = 0;
            a2i[i][0] = a2i[i][1] = 0; a2h[i][0] = a2h[i][1] = 0;
        }
        #pragma unroll 4
        for (int k = 0; k < OD; ++k) {
            float4 t0 = *reinterpret_cast<const float4*>(Wi0 + k * HD + 4 * l);
            float4 t1 = *reinterpret_cast<const float4*>(Wi1 + k * HD + 4 * l);
            float4 t2 = *reinterpret_cast<const float4*>(Wi2 + k * HD + 4 * l);
            ull w00 = pack2(t0.x, t0.y), w01 = pack2(t0.z, t0.w);
            ull w10 = pack2(t1.x, t1.y), w11 = pack2(t1.z, t1.w);
            ull w20 = pack2(t2.x, t2.y), w21 = pack2(t2.z, t2.w);
            #pragma unroll
            for (int i = 0; i < 4; ++i) {
                ull pv = dup2(ps[rb + i][k]);
                a0[i][0]  = fma2(pv, w00, a0[i][0]);  a0[i][1]  = fma2(pv, w01, a0[i][1]);
                a1[i][0]  = fma2(pv, w10, a1[i][0]);  a1[i][1]  = fma2(pv, w11, a1[i][1]);
                a2i[i][0] = fma2(pv, w20, a2i[i][0]); a2i[i][1] = fma2(pv, w21, a2i[i][1]);
            }
        }
        #pragma unroll 4
        for (int k = 0; k < HD; ++k) {
            float4 t0 = *reinterpret_cast<const float4*>(Wh0 + k * HD + 4 * l);
            float4 t1 = *reinterpret_cast<const float4*>(Wh1 + k * HD + 4 * l);
            float4 t2 = *reinterpret_cast<const float4*>(Wh2 + k * HD + 4 * l);
            ull w00 = pack2(t0.x, t0.y), w01 = pack2(t0.z, t0.w);
            ull w10 = pack2(t1.x, t1.y), w11 = pack2(t1.z, t1.w);
            ull w20 = pack2(t2.x, t2.y), w21 = pack2(t2.z, t2.w);
            #pragma unroll
            for (int i = 0; i < 4; ++i) {
                ull hv = dup2(hs[rb + i][k]);
                a0[i][0]  = fma2(hv, w00, a0[i][0]);  a0[i][1]  = fma2(hv, w01, a0[i][1]);
                a1[i][0]  = fma2(hv, w10, a1[i][0]);  a1[i][1]  = fma2(hv, w11, a1[i][1]);
                a2h[i][0] = fma2(hv, w20, a2h[i][0]); a2h[i][1] = fma2(hv, w21, a2h[i][1]);
            }
        }

        float bi0[4], bi1[4], bi2[4], bh0[4], bh1[4], bh2[4];
        { float4 t = *reinterpret_cast<const float4*>(bi + 0 * HD + 4 * l); bi0[0]=t.x; bi0[1]=t.y; bi0[2]=t.z; bi0[3]=t.w; }
        { float4 t = *reinterpret_cast<const float4*>(bi + 1 * HD + 4 * l); bi1[0]=t.x; bi1[1]=t.y; bi1[2]=t.z; bi1[3]=t.w; }
        { float4 t = *reinterpret_cast<const float4*>(bi + 2 * HD + 4 * l); bi2[0]=t.x; bi2[1]=t.y; bi2[2]=t.z; bi2[3]=t.w; }
        { float4 t = *reinterpret_cast<const float4*>(bh + 0 * HD + 4 * l); bh0[0]=t.x; bh0[1]=t.y; bh0[2]=t.z; bh0[3]=t.w; }
        { float4 t = *reinterpret_cast<const float4*>(bh + 1 * HD + 4 * l); bh1[0]=t.x; bh1[1]=t.y; bh1[2]=t.z; bh1[3]=t.w; }
        { float4 t = *reinterpret_cast<const float4*>(bh + 2 * HD + 4 * l); bh2[0]=t.x; bh2[1]=t.y; bh2[2]=t.z; bh2[3]=t.w; }

        float hf[4][4];
        #pragma unroll
        for (int i = 0; i < 4; ++i) {
            #pragma unroll
            for (int pr = 0; pr < 2; ++pr) {
                float g0a, g0b, g1a, g1b, nia, nib, nha, nhb;
                unpack2(a0[i][pr], g0a, g0b);  unpack2(a1[i][pr], g1a, g1b);
                unpack2(a2i[i][pr], nia, nib); unpack2(a2h[i][pr], nha, nhb);
                int j0 = pr * 2;
                {
                    float rg = sigm(g0a + bi0[j0] + bh0[j0]);
                    float zg = sigm(g1a + bi1[j0] + bh1[j0]);
                    float ng = tanhf(nia + bi2[j0] + rg * (nha + bh2[j0]));
                    float hv = hs[rb + i][4 * l + j0];
                    hf[i][j0] = (1.0f - zg) * ng + zg * hv;
                }
                {
                    float rg = sigm(g0b + bi0[j0 + 1] + bh0[j0 + 1]);
                    float zg = sigm(g1b + bi1[j0 + 1] + bh1[j0 + 1]);
                    float ng = tanhf(nib + bi2[j0 + 1] + rg * (nhb + bh2[j0 + 1]));
                    float hv = hs[rb + i][4 * l + j0 + 1];
                    hf[i][j0 + 1] = (1.0f - zg) * ng + zg * hv;
                }
            }
        }
        __syncwarp();   // warp's lanes finished reading rows rb..rb+3
        #pragma unroll
        for (int i = 0; i < 4; ++i)
            #pragma unroll
            for (int j = 0; j < 4; ++j) hs[rb + i][4 * l + j] = hf[i][j];
        __syncwarp();
    }

    // ---- phase 2: h2 = tanh(h_f @ ufw + ufb + h_a @ uaw + uab) ----
    {
        ull acc[4][2];
        {
            float4 tf = *reinterpret_cast<const float4*>(ufb + 4 * l);
            float4 ta = *reinterpret_cast<const float4*>(uab + 4 * l);
            ull b0 = pack2(tf.x + ta.x, tf.y + ta.y);
            ull b1 = pack2(tf.z + ta.z, tf.w + ta.w);
            #pragma unroll
            for (int i = 0; i < 4; ++i) { acc[i][0] = b0; acc[i][1] = b1; }
        }
        #pragma unroll 4
        for (int k = 0; k < HD; ++k) {
            float4 tf = *reinterpret_cast<const float4*>(ufw + k * HD + 4 * l);
            float4 ta = *reinterpret_cast<const float4*>(uaw + k * HD + 4 * l);
            ull wf0 = pack2(tf.x, tf.y), wf1 = pack2(tf.z, tf.w);
            ull wa0 = pack2(ta.x, ta.y), wa1 = pack2(ta.z, ta.w);
            #pragma unroll
            for (int i = 0; i < 4; ++i) {
                ull hfv = dup2(hs[rb + i][k]);
                ull hav = dup2(has[rb + i][k]);
                acc[i][0] = fma2(hfv, wf0, acc[i][0]); acc[i][1] = fma2(hfv, wf1, acc[i][1]);
                acc[i][0] = fma2(hav, wa0, acc[i][0]); acc[i][1] = fma2(hav, wa1, acc[i][1]);
            }
        }
        #pragma unroll
        for (int i = 0; i < 4; ++i) {
            float x0, x1, x2, x3;
            unpack2(acc[i][0], x0, x1); unpack2(acc[i][1], x2, x3);
            *reinterpret_cast<float4*>(hout + (size_t)(row0 + rb + i) * HD + 4 * l)
                = make_float4(tanhf(x0), tanhf(x1), tanhf(x2), tanhf(x3));
        }
    }
}

// ============================================================
// host: preorder scheduler
// ============================================================
struct SchedCtx {
    const float* in[18];
    float* out;
    float *ha, *hai, *prob;
    int B, grid, idx;
};

static void sched_node(SchedCtx& S, int lvl, const float* hA, int d)
{
    node_kernel<<<S.grid, NT>>>(hA,
        S.in[3], S.in[4],                       // h2o_w, h2o_b
        S.in[5], S.in[6], S.in[7], S.in[8],     // gru_a wi, bi, wh, bh
        S.out + (size_t)S.idx * S.B * OD,
        S.prob + (size_t)lvl * S.B * OD,
        S.hai  + (size_t)lvl * S.B * HD);
    S.idx++;
    if (d > 0) {
        const float* h_ai = S.hai + (size_t)lvl * S.B * HD;
        sched_node(S, lvl + 1, h_ai, d - 1);                       // first child
        frat_kernel<<<S.grid, NT>>>(
            S.prob + (size_t)(lvl + 1) * S.B * OD,                  // first child's probs
            h_ai, hA,
            S.in[9], S.in[10], S.in[11], S.in[12],                  // gru_f wi, bi, wh, bh
            S.in[15], S.in[16],                                     // u_f_w, u_f_b
            S.in[13], S.in[14],                                     // u_a_w, u_a_b
            S.ha + (size_t)(lvl + 1) * S.B * HD);
        sched_node(S, lvl + 1, S.ha + (size_t)(lvl + 1) * S.B * HD, d - 1);  // second child
    }
}

extern "C" void kernel_launch(void* const* d_in, const int* in_sizes, int n_in,
                              void* d_out, int out_size)
{
    SchedCtx S;
    for (int i = 0; i < n_in && i < 18; ++i) S.in[i] = (const float*)d_in[i];
    S.out = (float*)d_out;
    S.B = in_sizes[0] / IND;
    if (S.B <= 0 || S.B > BMAX) return;
    S.grid = S.B / TILE;
    S.idx = 0;

    int n_nodes = out_size / (S.B * OD);
    int depth = 0; { int nn = 1; while (nn < n_nodes && depth < MAXLVL - 1) { nn = 2 * nn + 1; depth++; } }

    cudaGetSymbolAddress((void**)&S.ha,   g_ha);
    cudaGetSymbolAddress((void**)&S.hai,  g_hai);
    cudaGetSymbolAddress((void**)&S.prob, g_prob);

    init_kernel<<<S.grid, NT>>>(S.in[0], S.in[1], S.in[2], S.ha);
    sched_node(S, 0, S.ha, depth);
}